// round 2
// baseline (speedup 1.0000x reference)
#include <cuda_runtime.h>
#include <cstdint>

// VectorQuantizer: N=65536 rows (z), K=8192 codes (emb), D=256.
// d(n,k) = fl(fl(z2[n] + e2[k]) - 2*dot(n,k)), argmin_k with first-index ties,
// replicating the reference's fp32 rounding (z2~256 quantizes the distances).
// Outputs (concat f32): quantized [N,D], straight_through=(q-z)+z [N,D], indices [N].

typedef unsigned long long u64;

#define KC   8192
#define DD   256
#define BM   64
#define PADF 258          // padded floats per smem row (conflict-free LDS.64)
#define NTILES (KC / 64)

__device__ float g_e2[KC];

__global__ void e2_kernel(const float* __restrict__ emb) {
    int c = blockIdx.x * blockDim.x + threadIdx.x;
    if (c < KC) {
        const float* r = emb + (size_t)c * DD;
        float s = 0.f;
        #pragma unroll 8
        for (int d = 0; d < DD; ++d) s = __fadd_rn(s, __fmul_rn(r[d], r[d]));
        g_e2[c] = s;
    }
}

__device__ __forceinline__ void ffma2(u64& acc, u64 a, u64 b) {
    asm volatile("fma.rn.f32x2 %0, %1, %2, %0;" : "+l"(acc) : "l"(a), "l"(b));
}

__device__ __forceinline__ void prefetch_tile(const float* __restrict__ emb,
                                              int tile, float* esbuf, int tid) {
    int cbase = tile * 64;
    uint32_t sbase = (uint32_t)__cvta_generic_to_shared(esbuf);
    // 64 codes x 256 floats = 8192 float2 chunks, 256 threads -> 32 each
    #pragma unroll 4
    for (int q = tid; q < 64 * 128; q += 256) {
        int r  = q >> 7;          // code row in tile
        int d2 = q & 127;         // float2 index within row
        const float* src = emb + (size_t)(cbase + r) * DD + d2 * 2;
        uint32_t dst = sbase + (uint32_t)((r * PADF + d2 * 2) * 4);
        asm volatile("cp.async.ca.shared.global [%0], [%1], 8;\n" :: "r"(dst), "l"(src));
    }
    asm volatile("cp.async.commit_group;\n" ::);
}

__global__ __launch_bounds__(256, 1)
void vq_main(const float* __restrict__ z, const float* __restrict__ emb,
             float* __restrict__ oq, float* __restrict__ ost,
             float* __restrict__ oidx)
{
    extern __shared__ char smem_raw[];
    float* zs   = (float*)smem_raw;            // BM * PADF
    float* es0  = zs  + BM * PADF;             // BM * PADF
    float* es1  = es0 + BM * PADF;             // BM * PADF
    float* z2s  = es1 + BM * PADF;             // 64
    float* redD = z2s + 64;                    // 64*16
    int*   redI = (int*)(redD + 64 * 16);      // 64*16
    int*   fidx = redI + 64 * 16;              // 64

    const int tid = threadIdx.x;
    const int tx  = tid & 15;
    const int ty  = tid >> 4;
    const int rowbase = blockIdx.x * BM;

    // ---- load z tile [64 x 256] into padded smem ----
    {
        const float4* zg = (const float4*)(z + (size_t)rowbase * DD);
        #pragma unroll 4
        for (int q = tid; q < BM * DD / 4; q += 256) {
            int r  = q >> 6;        // 64 float4 per row
            int d4 = q & 63;
            float4 v = zg[r * 64 + d4];
            float* dst = zs + r * PADF + d4 * 4;
            dst[0] = v.x; dst[1] = v.y; dst[2] = v.z; dst[3] = v.w;
        }
    }
    __syncthreads();

    // ---- z2 per row (ulp-level differences vs ref are a uniform grid shift) ----
    if (tid < BM) {
        const float* zr = zs + tid * PADF;
        float s = 0.f;
        #pragma unroll 8
        for (int d = 0; d < DD; ++d) s = __fadd_rn(s, __fmul_rn(zr[d], zr[d]));
        z2s[tid] = s;
    }

    // ---- prefetch first e-tile ----
    prefetch_tile(emb, 0, es0, tid);
    asm volatile("cp.async.wait_group 0;\n" ::);
    __syncthreads();

    float best[4];
    int   bidx[4];
    #pragma unroll
    for (int i = 0; i < 4; ++i) { best[i] = 3.4e38f; bidx[i] = 0x7fffffff; }

    const u64* zp[4];
    #pragma unroll
    for (int i = 0; i < 4; ++i) zp[i] = (const u64*)(zs + (ty + 16 * i) * PADF);

    for (int t = 0; t < NTILES; ++t) {
        float* cur = (t & 1) ? es1 : es0;
        float* nxt = (t & 1) ? es0 : es1;
        if (t + 1 < NTILES) prefetch_tile(emb, t + 1, nxt, tid);

        const u64* ep[4];
        #pragma unroll
        for (int j = 0; j < 4; ++j) ep[j] = (const u64*)(cur + (tx + 16 * j) * PADF);

        u64 acc[4][4];
        #pragma unroll
        for (int i = 0; i < 4; ++i)
            #pragma unroll
            for (int j = 0; j < 4; ++j) acc[i][j] = 0ull;

        #pragma unroll 2
        for (int d2 = 0; d2 < DD / 2; ++d2) {
            u64 za[4], eb[4];
            #pragma unroll
            for (int i = 0; i < 4; ++i) za[i] = zp[i][d2];
            #pragma unroll
            for (int j = 0; j < 4; ++j) eb[j] = ep[j][d2];
            #pragma unroll
            for (int i = 0; i < 4; ++i)
                #pragma unroll
                for (int j = 0; j < 4; ++j) ffma2(acc[i][j], za[i], eb[j]);
        }

        // ---- epilogue: quantized distance + running argmin ----
        int cb = t * 64;
        float e2v[4];
        #pragma unroll
        for (int j = 0; j < 4; ++j) e2v[j] = g_e2[cb + tx + 16 * j];
        #pragma unroll
        for (int i = 0; i < 4; ++i) {
            float z2 = z2s[ty + 16 * i];
            #pragma unroll
            for (int j = 0; j < 4; ++j) {
                float lo  = __uint_as_float((uint32_t)(acc[i][j] & 0xffffffffu));
                float hi  = __uint_as_float((uint32_t)(acc[i][j] >> 32));
                float dot = __fadd_rn(lo, hi);
                float tt  = __fadd_rn(z2, e2v[j]);        // fl(z2 + e2)
                float dd  = __fadd_rn(tt, -2.0f * dot);   // fl(t - 2*dot); 2*dot exact
                int   c   = cb + tx + 16 * j;
                if (dd < best[i] || (dd == best[i] && c < bidx[i])) {
                    best[i] = dd; bidx[i] = c;
                }
            }
        }

        if (t + 1 < NTILES) asm volatile("cp.async.wait_group 0;\n" ::);
        __syncthreads();
    }

    // ---- cross-thread argmin reduction per row (first-index tie-break) ----
    #pragma unroll
    for (int i = 0; i < 4; ++i) {
        int r = ty + 16 * i;
        redD[r * 16 + tx] = best[i];
        redI[r * 16 + tx] = bidx[i];
    }
    __syncthreads();
    if (tid < BM) {
        float bd = redD[tid * 16];
        int   bi = redI[tid * 16];
        #pragma unroll
        for (int s = 1; s < 16; ++s) {
            float d  = redD[tid * 16 + s];
            int   ix = redI[tid * 16 + s];
            if (d < bd || (d == bd && ix < bi)) { bd = d; bi = ix; }
        }
        fidx[tid] = bi;
    }
    __syncthreads();

    // ---- outputs: quantized, straight_through = (q - z) + z, indices ----
    for (int r = 0; r < BM; ++r) {
        int    idx = fidx[r];
        size_t n   = (size_t)rowbase + r;
        float  qv  = emb[(size_t)idx * DD + tid];
        float  zv  = zs[r * PADF + tid];
        if (oq)  oq[n * DD + tid]  = qv;
        if (ost) ost[n * DD + tid] = __fadd_rn(__fadd_rn(qv, -zv), zv);
    }
    if (oidx && tid < BM)
        oidx[(size_t)rowbase + tid] = (float)fidx[tid];
}

extern "C" void kernel_launch(void* const* d_in, const int* in_sizes, int n_in,
                              void* d_out, int out_size)
{
    const float* z   = (const float*)d_in[0];
    const float* emb = (const float*)d_in[1];
    float* out = (float*)d_out;

    const int N = in_sizes[0] / DD;        // 65536
    const size_t ND = (size_t)N * DD;

    // Layout inference from out_size: [quantized | straight_through | indices]
    float *oq = nullptr, *ost = nullptr, *oidx = nullptr;
    long osz = (long)out_size;
    if (osz >= (long)(2 * ND + N)) { oq = out; ost = out + ND; oidx = out + 2 * ND; }
    else if (osz == (long)(ND + N)) { oq = out; oidx = out + ND; }
    else if (osz == (long)ND)       { oq = out; }
    else if (osz == (long)N)        { oidx = out; }
    else                            { oq = out; }

    e2_kernel<<<(KC + 255) / 256, 256>>>(emb);

    size_t smem = (size_t)(3 * BM * PADF) * 4   // zs + es0 + es1
                + 64 * 4                         // z2s
                + 64 * 16 * 4                    // redD
                + 64 * 16 * 4                    // redI
                + 64 * 4;                        // fidx
    cudaFuncSetAttribute(vq_main, cudaFuncAttributeMaxDynamicSharedMemorySize, (int)smem);
    vq_main<<<N / BM, 256, smem>>>(z, emb, oq, ost, oidx);
}

// round 3
// speedup vs baseline: 1.0619x; 1.0619x over previous
#include <cuda_runtime.h>
#include <cstdint>

// VectorQuantizer: N=65536 rows (z), K=8192 codes (emb), D=256.
// d(n,k) = fl(fl(z2[n] + e2[k]) - 2*dot(n,k)), argmin_k with first-index ties,
// replicating the reference's fp32 rounding (z2~256 quantizes the distances).
// R3: 8x4 register tile (f32x2), 128 thr/CTA, BM=64, BN=64 double-buffered.
// Per-(row,code) FP32 accumulation sequence is IDENTICAL to R2 (rel_err 0.0).

typedef unsigned long long u64;

#define KC   8192
#define DD   256
#define BM   64
#define BN   64
#define PADF 258          // padded floats per smem row (conflict-free LDS.64)
#define NTILES (KC / BN)
#define NTHR 128

__device__ float g_e2[KC];

__global__ void e2_kernel(const float* __restrict__ emb) {
    int c = blockIdx.x * blockDim.x + threadIdx.x;
    if (c < KC) {
        const float* r = emb + (size_t)c * DD;
        float s = 0.f;
        #pragma unroll 8
        for (int d = 0; d < DD; ++d) s = __fadd_rn(s, __fmul_rn(r[d], r[d]));
        g_e2[c] = s;
    }
}

__device__ __forceinline__ void ffma2(u64& acc, u64 a, u64 b) {
    asm volatile("fma.rn.f32x2 %0, %1, %2, %0;" : "+l"(acc) : "l"(a), "l"(b));
}

__device__ __forceinline__ void prefetch_tile(const float* __restrict__ emb,
                                              int tile, float* esbuf, int tid) {
    int cbase = tile * BN;
    uint32_t sbase = (uint32_t)__cvta_generic_to_shared(esbuf);
    // BN codes x 256 floats = BN*128 float2 chunks, 128 threads
    #pragma unroll 8
    for (int q = tid; q < BN * 128; q += NTHR) {
        int r  = q >> 7;          // code row in tile
        int d2 = q & 127;         // float2 index within row
        const float* src = emb + (size_t)(cbase + r) * DD + d2 * 2;
        uint32_t dst = sbase + (uint32_t)((r * PADF + d2 * 2) * 4);
        asm volatile("cp.async.ca.shared.global [%0], [%1], 8;\n" :: "r"(dst), "l"(src));
    }
    asm volatile("cp.async.commit_group;\n" ::);
}

__global__ __launch_bounds__(NTHR, 1)
void vq_main(const float* __restrict__ z, const float* __restrict__ emb,
             float* __restrict__ oq, float* __restrict__ ost,
             float* __restrict__ oidx)
{
    extern __shared__ char smem_raw[];
    float* zs   = (float*)smem_raw;            // BM * PADF
    float* es0  = zs  + BM * PADF;             // BN * PADF
    float* es1  = es0 + BN * PADF;             // BN * PADF
    float* z2s  = es1 + BN * PADF;             // BM
    float* redD = z2s + BM;                    // BM*16
    int*   redI = (int*)(redD + BM * 16);      // BM*16
    int*   fidx = redI + BM * 16;              // BM

    const int tid = threadIdx.x;
    const int tx  = tid & 15;                  // code lane: 0..15
    const int ty  = tid >> 4;                  // row lane: 0..7
    const int rowbase = blockIdx.x * BM;

    // ---- load z tile [64 x 256] into padded smem ----
    {
        const float4* zg = (const float4*)(z + (size_t)rowbase * DD);
        #pragma unroll 8
        for (int q = tid; q < BM * DD / 4; q += NTHR) {
            int r  = q >> 6;        // 64 float4 per row
            int d4 = q & 63;
            float4 v = zg[r * 64 + d4];
            float* dst = zs + r * PADF + d4 * 4;
            dst[0] = v.x; dst[1] = v.y; dst[2] = v.z; dst[3] = v.w;
        }
    }
    __syncthreads();

    // ---- z2 per row (ulp-level differences vs ref are a uniform grid shift) ----
    if (tid < BM) {
        const float* zr = zs + tid * PADF;
        float s = 0.f;
        #pragma unroll 8
        for (int d = 0; d < DD; ++d) s = __fadd_rn(s, __fmul_rn(zr[d], zr[d]));
        z2s[tid] = s;
    }

    // ---- prefetch first e-tile ----
    prefetch_tile(emb, 0, es0, tid);
    asm volatile("cp.async.wait_group 0;\n" ::);
    __syncthreads();

    float best[8];
    int   bidx[8];
    #pragma unroll
    for (int i = 0; i < 8; ++i) { best[i] = 3.4e38f; bidx[i] = 0x7fffffff; }

    const u64* zp[8];
    #pragma unroll
    for (int i = 0; i < 8; ++i) zp[i] = (const u64*)(zs + (ty + 8 * i) * PADF);

    for (int t = 0; t < NTILES; ++t) {
        float* cur = (t & 1) ? es1 : es0;
        float* nxt = (t & 1) ? es0 : es1;
        if (t + 1 < NTILES) prefetch_tile(emb, t + 1, nxt, tid);

        const u64* ep[4];
        #pragma unroll
        for (int j = 0; j < 4; ++j) ep[j] = (const u64*)(cur + (tx + 16 * j) * PADF);

        u64 acc[8][4];
        #pragma unroll
        for (int i = 0; i < 8; ++i)
            #pragma unroll
            for (int j = 0; j < 4; ++j) acc[i][j] = 0ull;

        #pragma unroll 4
        for (int d2 = 0; d2 < DD / 2; ++d2) {
            u64 za[8], eb[4];
            #pragma unroll
            for (int j = 0; j < 4; ++j) eb[j] = ep[j][d2];
            #pragma unroll
            for (int i = 0; i < 8; ++i) za[i] = zp[i][d2];
            #pragma unroll
            for (int i = 0; i < 8; ++i)
                #pragma unroll
                for (int j = 0; j < 4; ++j) ffma2(acc[i][j], za[i], eb[j]);
        }

        // ---- epilogue: quantized distance + running argmin ----
        int cb = t * BN;
        float e2v[4];
        #pragma unroll
        for (int j = 0; j < 4; ++j) e2v[j] = g_e2[cb + tx + 16 * j];
        #pragma unroll
        for (int i = 0; i < 8; ++i) {
            float z2 = z2s[ty + 8 * i];
            #pragma unroll
            for (int j = 0; j < 4; ++j) {
                float lo  = __uint_as_float((uint32_t)(acc[i][j] & 0xffffffffu));
                float hi  = __uint_as_float((uint32_t)(acc[i][j] >> 32));
                float dot = __fadd_rn(lo, hi);
                float tt  = __fadd_rn(z2, e2v[j]);        // fl(z2 + e2)
                float dd  = __fadd_rn(tt, -2.0f * dot);   // fl(t - 2*dot); 2*dot exact
                int   c   = cb + tx + 16 * j;
                if (dd < best[i] || (dd == best[i] && c < bidx[i])) {
                    best[i] = dd; bidx[i] = c;
                }
            }
        }

        if (t + 1 < NTILES) asm volatile("cp.async.wait_group 0;\n" ::);
        __syncthreads();
    }

    // ---- cross-thread argmin reduction per row (first-index tie-break) ----
    #pragma unroll
    for (int i = 0; i < 8; ++i) {
        int r = ty + 8 * i;
        redD[r * 16 + tx] = best[i];
        redI[r * 16 + tx] = bidx[i];
    }
    __syncthreads();
    if (tid < BM) {
        float bd = redD[tid * 16];
        int   bi = redI[tid * 16];
        #pragma unroll
        for (int s = 1; s < 16; ++s) {
            float d  = redD[tid * 16 + s];
            int   ix = redI[tid * 16 + s];
            if (d < bd || (d == bd && ix < bi)) { bd = d; bi = ix; }
        }
        fidx[tid] = bi;
    }
    __syncthreads();

    // ---- outputs: quantized, straight_through = (q - z) + z, indices ----
    for (int r = 0; r < BM; ++r) {
        int    idx = fidx[r];
        size_t n   = (size_t)rowbase + r;
        const float* er = emb + (size_t)idx * DD;
        #pragma unroll
        for (int h = 0; h < 2; ++h) {
            int c = tid + h * NTHR;
            float qv = __ldg(er + c);
            float zv = zs[r * PADF + c];
            if (oq)  oq[n * DD + c]  = qv;
            if (ost) ost[n * DD + c] = __fadd_rn(__fadd_rn(qv, -zv), zv);
        }
    }
    if (oidx && tid < BM)
        oidx[(size_t)rowbase + tid] = (float)fidx[tid];
}

extern "C" void kernel_launch(void* const* d_in, const int* in_sizes, int n_in,
                              void* d_out, int out_size)
{
    const float* z   = (const float*)d_in[0];
    const float* emb = (const float*)d_in[1];
    float* out = (float*)d_out;

    const int N = in_sizes[0] / DD;        // 65536
    const size_t ND = (size_t)N * DD;

    // Layout inference from out_size: [quantized | straight_through | indices]
    float *oq = nullptr, *ost = nullptr, *oidx = nullptr;
    long osz = (long)out_size;
    if (osz >= (long)(2 * ND + N)) { oq = out; ost = out + ND; oidx = out + 2 * ND; }
    else if (osz == (long)(ND + N)) { oq = out; oidx = out + ND; }
    else if (osz == (long)ND)       { oq = out; }
    else if (osz == (long)N)        { oidx = out; }
    else                            { oq = out; }

    e2_kernel<<<(KC + 255) / 256, 256>>>(emb);

    size_t smem = (size_t)((BM + 2 * BN) * PADF) * 4   // zs + es0 + es1
                + BM * 4                                // z2s
                + BM * 16 * 4                           // redD
                + BM * 16 * 4                           // redI
                + BM * 4;                               // fidx
    cudaFuncSetAttribute(vq_main, cudaFuncAttributeMaxDynamicSharedMemorySize, (int)smem);
    vq_main<<<N / BM, NTHR, smem>>>(z, emb, oq, ost, oidx);
}

// round 4
// speedup vs baseline: 1.0820x; 1.0189x over previous
#include <cuda_runtime.h>
#include <cstdint>

// VectorQuantizer: N=65536 rows (z), K=8192 codes (emb), D=256.
// d(n,k) = fl(fl(z2[n] + e2[k]) - 2*dot(n,k)), argmin_k with first-index ties,
// replicating the reference's fp32 rounding (z2~256 quantizes the distances).
// R4: 256 thr (8 warps/SM), BM=128 x BN=64, 8x4 f32x2 register tile,
// e-tile chunked over D (2 x 128 floats) + double buffering.
// Per-(row,code) FP32 accumulation order identical to R2/R3 (rel_err 0.0).

typedef unsigned long long u64;

#define KC    8192
#define DD    256
#define BM    128
#define BN    64
#define PADZ  258          // padded floats per z smem row
#define PADE  130          // padded floats per e-chunk smem row (128 + 2)
#define DCH   128          // floats per D-chunk
#define NCH   (DD / DCH)   // 2 chunks
#define NTILES (KC / BN)
#define NTHR  256

__device__ float g_e2[KC];

__global__ void e2_kernel(const float* __restrict__ emb) {
    int c = blockIdx.x * blockDim.x + threadIdx.x;
    if (c < KC) {
        const float* r = emb + (size_t)c * DD;
        float s = 0.f;
        #pragma unroll 8
        for (int d = 0; d < DD; ++d) s = __fadd_rn(s, __fmul_rn(r[d], r[d]));
        g_e2[c] = s;
    }
}

__device__ __forceinline__ void ffma2(u64& acc, u64 a, u64 b) {
    asm volatile("fma.rn.f32x2 %0, %1, %2, %0;" : "+l"(acc) : "l"(a), "l"(b));
}

// prefetch one (tile, chunk) of e: BN codes x DCH floats into esbuf [BN x PADE]
__device__ __forceinline__ void prefetch_chunk(const float* __restrict__ emb,
                                               int tile, int ch, float* esbuf, int tid) {
    int cbase = tile * BN;
    int dbase = ch * DCH;
    uint32_t sbase = (uint32_t)__cvta_generic_to_shared(esbuf);
    // BN*DCH/2 = 64*64 = 4096 float2 chunks, 256 threads -> 16 each
    #pragma unroll 4
    for (int q = tid; q < BN * (DCH / 2); q += NTHR) {
        int r  = q >> 6;          // code row in tile (DCH/2 = 64 float2 per row)
        int d2 = q & 63;          // float2 index within chunk
        const float* src = emb + (size_t)(cbase + r) * DD + dbase + d2 * 2;
        uint32_t dst = sbase + (uint32_t)((r * PADE + d2 * 2) * 4);
        asm volatile("cp.async.ca.shared.global [%0], [%1], 8;\n" :: "r"(dst), "l"(src));
    }
    asm volatile("cp.async.commit_group;\n" ::);
}

__global__ __launch_bounds__(NTHR, 1)
void vq_main(const float* __restrict__ z, const float* __restrict__ emb,
             float* __restrict__ oq, float* __restrict__ ost,
             float* __restrict__ oidx)
{
    extern __shared__ char smem_raw[];
    float* zs   = (float*)smem_raw;            // BM * PADZ  (132096 B)
    float* es0  = zs  + BM * PADZ;             // BN * PADE  (33280 B)
    float* es1  = es0 + BN * PADE;             // BN * PADE  (33280 B)
    float* z2s  = es1 + BN * PADE;             // BM
    int*   fidx = (int*)(z2s + BM);            // BM
    // reduction arrays alias the e buffers (used only after the main loop)
    float* redD = es0;                         // BM*16 floats (16KB < es0)
    int*   redI = (int*)es1;                   // BM*16 ints

    const int tid = threadIdx.x;
    const int tx  = tid & 15;                  // code lane: 0..15
    const int ty  = tid >> 4;                  // row lane: 0..15
    const int rowbase = blockIdx.x * BM;

    // ---- load z tile [128 x 256] into padded smem ----
    {
        const float4* zg = (const float4*)(z + (size_t)rowbase * DD);
        #pragma unroll 8
        for (int q = tid; q < BM * DD / 4; q += NTHR) {
            int r  = q >> 6;        // 64 float4 per row
            int d4 = q & 63;
            float4 v = zg[r * 64 + d4];
            float* dst = zs + r * PADZ + d4 * 4;
            dst[0] = v.x; dst[1] = v.y; dst[2] = v.z; dst[3] = v.w;
        }
    }
    __syncthreads();

    // ---- z2 per row (ulp-level differences vs ref are a uniform grid shift) ----
    if (tid < BM) {
        const float* zr = zs + tid * PADZ;
        float s = 0.f;
        #pragma unroll 8
        for (int d = 0; d < DD; ++d) s = __fadd_rn(s, __fmul_rn(zr[d], zr[d]));
        z2s[tid] = s;
    }

    // ---- prefetch first chunk ----
    prefetch_chunk(emb, 0, 0, es0, tid);
    asm volatile("cp.async.wait_group 0;\n" ::);
    __syncthreads();

    float best[8];
    int   bidx[8];
    #pragma unroll
    for (int i = 0; i < 8; ++i) { best[i] = 3.4e38f; bidx[i] = 0x7fffffff; }

    for (int t = 0; t < NTILES; ++t) {
        u64 acc[8][4];
        #pragma unroll
        for (int i = 0; i < 8; ++i)
            #pragma unroll
            for (int j = 0; j < 4; ++j) acc[i][j] = 0ull;

        #pragma unroll
        for (int ch = 0; ch < NCH; ++ch) {
            int stage = (t * NCH + ch) & 1;
            float* cur = stage ? es1 : es0;
            float* nxt = stage ? es0 : es1;
            // prefetch next (tile, chunk)
            int nt = t, nc = ch + 1;
            if (nc == NCH) { nt = t + 1; nc = 0; }
            bool more = (nt < NTILES);
            if (more) prefetch_chunk(emb, nt, nc, nxt, tid);

            // z pointers offset to this chunk's d-range
            const u64* zp[8];
            #pragma unroll
            for (int i = 0; i < 8; ++i)
                zp[i] = (const u64*)(zs + (ty + 16 * i) * PADZ + ch * DCH);
            const u64* ep[4];
            #pragma unroll
            for (int j = 0; j < 4; ++j)
                ep[j] = (const u64*)(cur + (tx + 16 * j) * PADE);

            #pragma unroll 4
            for (int d2 = 0; d2 < DCH / 2; ++d2) {
                u64 za[8], eb[4];
                #pragma unroll
                for (int j = 0; j < 4; ++j) eb[j] = ep[j][d2];
                #pragma unroll
                for (int i = 0; i < 8; ++i) za[i] = zp[i][d2];
                #pragma unroll
                for (int i = 0; i < 8; ++i)
                    #pragma unroll
                    for (int j = 0; j < 4; ++j) ffma2(acc[i][j], za[i], eb[j]);
            }

            if (more) asm volatile("cp.async.wait_group 0;\n" ::);
            __syncthreads();
        }

        // ---- epilogue: quantized distance + running argmin ----
        int cb = t * BN;
        float e2v[4];
        #pragma unroll
        for (int j = 0; j < 4; ++j) e2v[j] = g_e2[cb + tx + 16 * j];
        #pragma unroll
        for (int i = 0; i < 8; ++i) {
            float z2 = z2s[ty + 16 * i];
            #pragma unroll
            for (int j = 0; j < 4; ++j) {
                float lo  = __uint_as_float((uint32_t)(acc[i][j] & 0xffffffffu));
                float hi  = __uint_as_float((uint32_t)(acc[i][j] >> 32));
                float dot = __fadd_rn(lo, hi);
                float tt  = __fadd_rn(z2, e2v[j]);        // fl(z2 + e2)
                float dd  = __fadd_rn(tt, -2.0f * dot);   // fl(t - 2*dot); 2*dot exact
                int   c   = cb + tx + 16 * j;
                if (dd < best[i] || (dd == best[i] && c < bidx[i])) {
                    best[i] = dd; bidx[i] = c;
                }
            }
        }
    }

    // ---- cross-thread argmin reduction per row (first-index tie-break) ----
    __syncthreads();   // ensure all compute done before aliasing e buffers
    #pragma unroll
    for (int i = 0; i < 8; ++i) {
        int r = ty + 16 * i;
        redD[r * 16 + tx] = best[i];
        redI[r * 16 + tx] = bidx[i];
    }
    __syncthreads();
    if (tid < BM) {
        float bd = redD[tid * 16];
        int   bi = redI[tid * 16];
        #pragma unroll
        for (int s = 1; s < 16; ++s) {
            float d  = redD[tid * 16 + s];
            int   ix = redI[tid * 16 + s];
            if (d < bd || (d == bd && ix < bi)) { bd = d; bi = ix; }
        }
        fidx[tid] = bi;
    }
    __syncthreads();

    // ---- outputs: quantized, straight_through = (q - z) + z, indices ----
    for (int r = 0; r < BM; ++r) {
        int    idx = fidx[r];
        size_t n   = (size_t)rowbase + r;
        float  qv  = __ldg(emb + (size_t)idx * DD + tid);
        float  zv  = zs[r * PADZ + tid];
        if (oq)  oq[n * DD + tid]  = qv;
        if (ost) ost[n * DD + tid] = __fadd_rn(__fadd_rn(qv, -zv), zv);
    }
    if (oidx && tid < BM)
        oidx[(size_t)rowbase + tid] = (float)fidx[tid];
}

extern "C" void kernel_launch(void* const* d_in, const int* in_sizes, int n_in,
                              void* d_out, int out_size)
{
    const float* z   = (const float*)d_in[0];
    const float* emb = (const float*)d_in[1];
    float* out = (float*)d_out;

    const int N = in_sizes[0] / DD;        // 65536
    const size_t ND = (size_t)N * DD;

    // Layout inference from out_size: [quantized | straight_through | indices]
    float *oq = nullptr, *ost = nullptr, *oidx = nullptr;
    long osz = (long)out_size;
    if (osz >= (long)(2 * ND + N)) { oq = out; ost = out + ND; oidx = out + 2 * ND; }
    else if (osz == (long)(ND + N)) { oq = out; oidx = out + ND; }
    else if (osz == (long)ND)       { oq = out; }
    else if (osz == (long)N)        { oidx = out; }
    else                            { oq = out; }

    e2_kernel<<<(KC + 255) / 256, 256>>>(emb);

    size_t smem = (size_t)(BM * PADZ + 2 * BN * PADE) * 4   // zs + es0 + es1
                + BM * 4                                     // z2s
                + BM * 4;                                    // fidx
    cudaFuncSetAttribute(vq_main, cudaFuncAttributeMaxDynamicSharedMemorySize, (int)smem);
    vq_main<<<N / BM, NTHR, smem>>>(z, emb, oq, ost, oidx);
}

// round 6
// speedup vs baseline: 1.2702x; 1.1740x over previous
#include <cuda_runtime.h>
#include <cuda_bf16.h>
#include <cstdint>

// VectorQuantizer N=65536, K=8192, D=256.
// R6: bf16 mma.sync (HMMA) GEMM as argmin FILTER (window W), exact fp32
// rescore of candidates replicating R2 arithmetic bit-for-bit (rel_err 0.0).
// (tcgen05 is unavailable: harness lowers to plain sm_103.)

typedef unsigned long long u64;
typedef uint32_t u32;

#define NN     65536
#define KC     8192
#define DD     256
#define BM     128
#define BN     64
#define NTILES (KC / BN)     // 128
#define NTHR   256
#define CAP    32
#define WIN    6e-4f
#define STRD   264           // bf16 elems per smem row (528 B, conflict-free)

__device__ __nv_bfloat16 g_zbf[(size_t)NN * DD];
__device__ __nv_bfloat16 g_ebf[(size_t)KC * DD];
__device__ float g_z2[NN];
__device__ float g_e2[KC];

// smem byte offsets
#define SA    0
#define SB0   (SA + BM * STRD * 2)       // 67584
#define SB1   (SB0 + BN * STRD * 2)      // 101376
#define SE20  (SB1 + BN * STRD * 2)      // 135168
#define SE21  (SE20 + 256)               // 135424
#define SZ2   (SE21 + 256)               // 135680
#define SMIN  (SZ2 + BM * 4)             // 136192
#define SCNT  (SMIN + BM * 4)            // 136704
#define SCD   (SCNT + BM * 4)            // 137216
#define SCK   (SCD + BM * CAP * 4)       // 153600
#define SFI   (SCK + BM * CAP * 4)       // 169984
#define STOT  (SFI + BM * 4)             // 170496

__device__ __forceinline__ u32 s2u(const void* p) {
    u32 a;
    asm("{ .reg .u64 t; cvta.to.shared.u64 t, %1; cvt.u32.u64 %0, t; }"
        : "=r"(a) : "l"(p));
    return a;
}
__device__ __forceinline__ void cpa16(u32 dst, const void* src) {
    asm volatile("cp.async.ca.shared.global [%0], [%1], 16;\n" :: "r"(dst), "l"(src));
}
__device__ __forceinline__ void mma16816(float* c, const u32* a, const u32* b) {
    asm volatile("mma.sync.aligned.m16n8k16.row.col.f32.bf16.bf16.f32 "
                 "{%0,%1,%2,%3}, {%4,%5,%6,%7}, {%8,%9}, {%0,%1,%2,%3};"
                 : "+f"(c[0]), "+f"(c[1]), "+f"(c[2]), "+f"(c[3])
                 : "r"(a[0]), "r"(a[1]), "r"(a[2]), "r"(a[3]),
                   "r"(b[0]), "r"(b[1]));
}

// ---------------- prep kernels (orders match R2's z2/e2 exactly) ----------------
__global__ void prep_e(const float* __restrict__ emb) {
    int k = blockIdx.x;
    const float* r = emb + (size_t)k * DD;
    g_ebf[(size_t)k * DD + threadIdx.x] = __float2bfloat16_rn(r[threadIdx.x]);
    if (threadIdx.x == 0) {
        float s = 0.f;
        #pragma unroll 8
        for (int d = 0; d < DD; ++d) s = __fadd_rn(s, __fmul_rn(r[d], r[d]));
        g_e2[k] = s;
    }
}
__global__ void prep_z(const float* __restrict__ z) {
    int n = blockIdx.x;
    const float* r = z + (size_t)n * DD;
    g_zbf[(size_t)n * DD + threadIdx.x] = __float2bfloat16_rn(r[threadIdx.x]);
    if (threadIdx.x == 0) {
        float s = 0.f;
        #pragma unroll 8
        for (int d = 0; d < DD; ++d) s = __fadd_rn(s, __fmul_rn(r[d], r[d]));
        g_z2[n] = s;
    }
}

// ---------------- main kernel ----------------
__global__ __launch_bounds__(NTHR, 1)
void vq_main(const float* __restrict__ z, const float* __restrict__ emb,
             float* __restrict__ oq, float* __restrict__ ost,
             float* __restrict__ oidx)
{
    extern __shared__ char sm[];
    const u32 smb = s2u(sm);
    __nv_bfloat16* As = (__nv_bfloat16*)(sm + SA);
    float* z2s    = (float*)(sm + SZ2);
    int*   rowMin = (int*)(sm + SMIN);
    int*   cnt    = (int*)(sm + SCNT);
    float* candD  = (float*)(sm + SCD);
    int*   candK  = (int*)(sm + SCK);
    int*   fidx   = (int*)(sm + SFI);

    const int tid  = threadIdx.x;
    const int wid  = tid >> 5;
    const int lane = tid & 31;
    const int rowbase = blockIdx.x * BM;
    const int Rw = (wid & 3) * 32;      // warp M offset
    const int Cw = (wid >> 2) * 32;     // warp N offset

    if (tid < BM) {
        rowMin[tid] = 0x7f7fffff;       // +FLT_MAX bits (distances are positive)
        cnt[tid] = 0;
        z2s[tid] = g_z2[rowbase + tid];
    }

    // group 0: A tile + B tile 0 + e2 tile 0
    {
        const __nv_bfloat16* zb = g_zbf + (size_t)rowbase * DD;
        #pragma unroll 4
        for (int q = tid; q < BM * 32; q += NTHR) {
            int r = q >> 5, c = (q & 31) * 8;
            cpa16(smb + SA + (u32)((r * STRD + c) * 2), zb + (size_t)r * DD + c);
        }
        const __nv_bfloat16* eb = g_ebf;
        #pragma unroll 2
        for (int q = tid; q < BN * 32; q += NTHR) {
            int r = q >> 5, c = (q & 31) * 8;
            cpa16(smb + SB0 + (u32)((r * STRD + c) * 2), eb + (size_t)r * DD + c);
        }
        if (tid < 16) cpa16(smb + SE20 + tid * 16, g_e2 + tid * 4);
        asm volatile("cp.async.commit_group;\n" ::);
    }
    __syncthreads();   // rowMin/cnt/z2s init visible

    for (int t = 0; t < NTILES; ++t) {
        // prefetch tile t+1 (buffer (t+1)&1, safe: freed by sync at end of t-1)
        if (t + 1 < NTILES) {
            const __nv_bfloat16* eb = g_ebf + (size_t)(t + 1) * BN * DD;
            u32 bb  = smb + (((t + 1) & 1) ? SB1 : SB0);
            u32 e2d = smb + (((t + 1) & 1) ? SE21 : SE20);
            #pragma unroll 2
            for (int q = tid; q < BN * 32; q += NTHR) {
                int r = q >> 5, c = (q & 31) * 8;
                cpa16(bb + (u32)((r * STRD + c) * 2), eb + (size_t)r * DD + c);
            }
            if (tid < 16) cpa16(e2d + tid * 16, g_e2 + (t + 1) * BN + tid * 4);
            asm volatile("cp.async.commit_group;\n" ::);
            asm volatile("cp.async.wait_group 1;\n" ::);
        } else {
            asm volatile("cp.async.wait_group 0;\n" ::);
        }
        __syncthreads();

        const __nv_bfloat16* Bs  = (const __nv_bfloat16*)(sm + ((t & 1) ? SB1 : SB0));
        const float*         e2t = (const float*)(sm + ((t & 1) ? SE21 : SE20));

        float acc[2][4][4];
        #pragma unroll
        for (int mi = 0; mi < 2; ++mi)
            #pragma unroll
            for (int ni = 0; ni < 4; ++ni)
                #pragma unroll
                for (int c = 0; c < 4; ++c) acc[mi][ni][c] = 0.f;

        const __nv_bfloat16* Abase = As + (Rw + (lane >> 2)) * STRD + (lane & 3) * 2;
        const __nv_bfloat16* Bbase = Bs + (Cw + (lane >> 2)) * STRD + (lane & 3) * 2;

        #pragma unroll 4
        for (int ks = 0; ks < 16; ++ks) {
            int ko = ks * 16;
            u32 a[2][4], b[4][2];
            #pragma unroll
            for (int mi = 0; mi < 2; ++mi) {
                const __nv_bfloat16* p = Abase + mi * 16 * STRD + ko;
                a[mi][0] = *(const u32*)(p);
                a[mi][1] = *(const u32*)(p + 8 * STRD);
                a[mi][2] = *(const u32*)(p + 8);
                a[mi][3] = *(const u32*)(p + 8 * STRD + 8);
            }
            #pragma unroll
            for (int ni = 0; ni < 4; ++ni) {
                const __nv_bfloat16* p = Bbase + ni * 8 * STRD + ko;
                b[ni][0] = *(const u32*)(p);
                b[ni][1] = *(const u32*)(p + 8);
            }
            #pragma unroll
            for (int mi = 0; mi < 2; ++mi)
                #pragma unroll
                for (int ni = 0; ni < 4; ++ni)
                    mma16816(acc[mi][ni], a[mi], b[ni]);
        }

        // ---- epilogue: dv in-place, row-min update, windowed inserts ----
        int cb = t * BN;
        float e2loc[4][2];
        #pragma unroll
        for (int ni = 0; ni < 4; ++ni) {
            float2 v = *(const float2*)(e2t + Cw + ni * 8 + (lane & 3) * 2);
            e2loc[ni][0] = v.x; e2loc[ni][1] = v.y;
        }
        // pass 1: compute dv, update running row min
        #pragma unroll
        for (int mi = 0; mi < 2; ++mi) {
            #pragma unroll
            for (int s = 0; s < 2; ++s) {
                int r = Rw + mi * 16 + (lane >> 2) + 8 * s;
                float z2v = z2s[r];
                float mn = 3.4e38f;
                #pragma unroll
                for (int ni = 0; ni < 4; ++ni) {
                    #pragma unroll
                    for (int q = 0; q < 2; ++q) {
                        float dv = fmaf(-2.f, acc[mi][ni][2 * s + q], z2v + e2loc[ni][q]);
                        acc[mi][ni][2 * s + q] = dv;
                        mn = fminf(mn, dv);
                    }
                }
                if (__float_as_int(mn) < rowMin[r])
                    atomicMin(&rowMin[r], __float_as_int(mn));
            }
        }
        if (t == 0) __syncthreads();   // tile 0: establish thresholds before inserting
        // pass 2: inserts (threshold stale-conservative for t>0)
        #pragma unroll
        for (int mi = 0; mi < 2; ++mi) {
            #pragma unroll
            for (int s = 0; s < 2; ++s) {
                int r = Rw + mi * 16 + (lane >> 2) + 8 * s;
                float thr = __int_as_float(rowMin[r]) + WIN;
                #pragma unroll
                for (int ni = 0; ni < 4; ++ni) {
                    #pragma unroll
                    for (int q = 0; q < 2; ++q) {
                        float dv = acc[mi][ni][2 * s + q];
                        if (dv <= thr) {
                            int pos = atomicAdd(&cnt[r], 1);
                            if (pos < CAP) {
                                candD[r * CAP + pos] = dv;
                                candK[r * CAP + pos] = cb + Cw + ni * 8 + (lane & 3) * 2 + q;
                            }
                        }
                    }
                }
            }
        }
        __syncthreads();   // protect buffers + cand state before next prefetch
    }

    // ---- exact rescore (replicates R2 arithmetic exactly) ----
    if (tid < BM) {
        int r = tid;
        size_t n = (size_t)rowbase + r;
        int c = cnt[r];
        if (c > CAP) {
            fidx[r] = -1;              // overflow -> cooperative fallback below
        } else {
            float thrF = __int_as_float(rowMin[r]) + WIN;
            float z2e = g_z2[n];
            const float* zr = z + n * DD;
            float bd = 0.f; int bk = -1;
            for (int i = 0; i < c; ++i) {
                if (candD[r * CAP + i] > thrF) continue;
                int k = candK[r * CAP + i];
                const float* er = emb + (size_t)k * DD;
                float lo = 0.f, hi = 0.f;
                #pragma unroll 4
                for (int d2 = 0; d2 < DD / 2; ++d2) {
                    lo = __fmaf_rn(__ldg(zr + 2 * d2),     __ldg(er + 2 * d2),     lo);
                    hi = __fmaf_rn(__ldg(zr + 2 * d2 + 1), __ldg(er + 2 * d2 + 1), hi);
                }
                float dot = __fadd_rn(lo, hi);
                float tt  = __fadd_rn(z2e, g_e2[k]);
                float dd  = __fadd_rn(tt, -2.0f * dot);
                if (bk < 0 || dd < bd || (dd == bd && k < bk)) { bd = dd; bk = k; }
            }
            fidx[r] = bk;
        }
    }
    __syncthreads();

    // ---- overflow fallback: full exact scan (cold; cnt>CAP essentially never) ----
    {
        float* redD = (float*)(sm + SB0);
        int*   redI = (int*)(sm + SB0 + NTHR * 4);
        for (int r = 0; r < BM; ++r) {
            if (fidx[r] != -1) continue;          // uniform (smem)
            size_t n = (size_t)rowbase + r;
            const float* zr = z + n * DD;
            float z2e = g_z2[n];
            float bd = 0.f; int bk = -1;
            for (int k = tid; k < KC; k += NTHR) {
                const float* er = emb + (size_t)k * DD;
                float lo = 0.f, hi = 0.f;
                #pragma unroll 4
                for (int d2 = 0; d2 < DD / 2; ++d2) {
                    lo = __fmaf_rn(zr[2 * d2],     er[2 * d2],     lo);
                    hi = __fmaf_rn(zr[2 * d2 + 1], er[2 * d2 + 1], hi);
                }
                float dot = __fadd_rn(lo, hi);
                float dd  = __fadd_rn(__fadd_rn(z2e, g_e2[k]), -2.0f * dot);
                if (bk < 0 || dd < bd || (dd == bd && k < bk)) { bd = dd; bk = k; }
            }
            redD[tid] = bd; redI[tid] = bk;
            __syncthreads();
            if (tid == 0) {
                float B = redD[0]; int K2 = redI[0];
                for (int s2 = 1; s2 < NTHR; ++s2) {
                    float d = redD[s2]; int k2 = redI[s2];
                    if (k2 >= 0 && (K2 < 0 || d < B || (d == B && k2 < K2))) { B = d; K2 = k2; }
                }
                fidx[r] = K2;
            }
            __syncthreads();
        }
    }
    __syncthreads();

    // ---- outputs: quantized, straight_through = (q - z) + z, indices ----
    for (int r = 0; r < BM; ++r) {
        int    idx = fidx[r];
        size_t n   = (size_t)rowbase + r;
        float  qv  = __ldg(emb + (size_t)idx * DD + tid);
        float  zv  = __ldg(z + n * DD + tid);
        if (oq)  oq[n * DD + tid]  = qv;
        if (ost) ost[n * DD + tid] = __fadd_rn(__fadd_rn(qv, -zv), zv);
    }
    if (oidx && tid < BM)
        oidx[(size_t)rowbase + tid] = (float)fidx[tid];
}

extern "C" void kernel_launch(void* const* d_in, const int* in_sizes, int n_in,
                              void* d_out, int out_size)
{
    const float* z   = (const float*)d_in[0];
    const float* emb = (const float*)d_in[1];
    float* out = (float*)d_out;

    const int N = in_sizes[0] / DD;
    const size_t ND = (size_t)N * DD;

    float *oq = nullptr, *ost = nullptr, *oidx = nullptr;
    long osz = (long)out_size;
    if (osz >= (long)(2 * ND + N)) { oq = out; ost = out + ND; oidx = out + 2 * ND; }
    else if (osz == (long)(ND + N)) { oq = out; oidx = out + ND; }
    else if (osz == (long)ND)       { oq = out; }
    else if (osz == (long)N)        { oidx = out; }
    else                            { oq = out; }

    prep_e<<<KC, DD>>>(emb);
    prep_z<<<N, DD>>>(z);

    cudaFuncSetAttribute(vq_main, cudaFuncAttributeMaxDynamicSharedMemorySize, STOT);
    vq_main<<<N / BM, NTHR, STOT>>>(z, emb, oq, ost, oidx);
}

// round 7
// speedup vs baseline: 1.2914x; 1.0167x over previous
#include <cuda_runtime.h>
#include <cuda_bf16.h>
#include <cstdint>

// VectorQuantizer N=65536, K=8192, D=256.
// R7: bf16 mma.sync filter with ldmatrix fragment loads (4 LDSM.x4 per k-step
// instead of 16 scalar LDS), exact fp32 rescore replicating R2 arithmetic
// bit-for-bit (rel_err 0.0). Warp tile m32n32, CTA tile 128x64, double-buffered.

typedef unsigned long long u64;
typedef uint32_t u32;

#define NN     65536
#define KC     8192
#define DD     256
#define BM     128
#define BN     64
#define NTILES (KC / BN)     // 128
#define NTHR   256
#define CAP    32
#define WIN    6e-4f
#define STRD   264           // bf16 elems per smem row (528 B; 4-bank row stagger)

__device__ __nv_bfloat16 g_zbf[(size_t)NN * DD];
__device__ __nv_bfloat16 g_ebf[(size_t)KC * DD];
__device__ float g_z2[NN];
__device__ float g_e2[KC];

// smem byte offsets
#define SA    0
#define SB0   (SA + BM * STRD * 2)       // 67584
#define SB1   (SB0 + BN * STRD * 2)      // 101376
#define SE20  (SB1 + BN * STRD * 2)      // 135168
#define SE21  (SE20 + 256)               // 135424
#define SZ2   (SE21 + 256)               // 135680
#define SMIN  (SZ2 + BM * 4)             // 136192
#define SCNT  (SMIN + BM * 4)            // 136704
#define SCD   (SCNT + BM * 4)            // 137216
#define SCK   (SCD + BM * CAP * 4)       // 153600
#define SFI   (SCK + BM * CAP * 4)       // 169984
#define STOT  (SFI + BM * 4)             // 170496

__device__ __forceinline__ u32 s2u(const void* p) {
    u32 a;
    asm("{ .reg .u64 t; cvta.to.shared.u64 t, %1; cvt.u32.u64 %0, t; }"
        : "=r"(a) : "l"(p));
    return a;
}
__device__ __forceinline__ void cpa16(u32 dst, const void* src) {
    asm volatile("cp.async.ca.shared.global [%0], [%1], 16;\n" :: "r"(dst), "l"(src));
}
__device__ __forceinline__ void ldsm4(u32* r, u32 saddr) {
    asm volatile("ldmatrix.sync.aligned.m8n8.x4.shared.b16 {%0,%1,%2,%3}, [%4];"
                 : "=r"(r[0]), "=r"(r[1]), "=r"(r[2]), "=r"(r[3]) : "r"(saddr));
}
__device__ __forceinline__ void mma16816(float* c, const u32* a, const u32* b) {
    asm volatile("mma.sync.aligned.m16n8k16.row.col.f32.bf16.bf16.f32 "
                 "{%0,%1,%2,%3}, {%4,%5,%6,%7}, {%8,%9}, {%0,%1,%2,%3};"
                 : "+f"(c[0]), "+f"(c[1]), "+f"(c[2]), "+f"(c[3])
                 : "r"(a[0]), "r"(a[1]), "r"(a[2]), "r"(a[3]),
                   "r"(b[0]), "r"(b[1]));
}

// ---------------- prep kernels (sequential sum order preserved!) ----------------
__global__ void prep_e(const float* __restrict__ emb) {
    int k = blockIdx.x, lane = threadIdx.x;
    const float* r = emb + (size_t)k * DD;
    #pragma unroll
    for (int i = 0; i < DD / 32; ++i)
        g_ebf[(size_t)k * DD + lane + i * 32] = __float2bfloat16_rn(r[lane + i * 32]);
    if (lane == 0) {
        float s = 0.f;
        #pragma unroll 8
        for (int d = 0; d < DD; ++d) s = __fadd_rn(s, __fmul_rn(r[d], r[d]));
        g_e2[k] = s;
    }
}
__global__ void prep_z(const float* __restrict__ z) {
    int n = blockIdx.x, lane = threadIdx.x;
    const float* r = z + (size_t)n * DD;
    #pragma unroll
    for (int i = 0; i < DD / 32; ++i)
        g_zbf[(size_t)n * DD + lane + i * 32] = __float2bfloat16_rn(r[lane + i * 32]);
    if (lane == 0) {
        float s = 0.f;
        #pragma unroll 8
        for (int d = 0; d < DD; ++d) s = __fadd_rn(s, __fmul_rn(r[d], r[d]));
        g_z2[n] = s;
    }
}

// ---------------- main kernel ----------------
__global__ __launch_bounds__(NTHR, 1)
void vq_main(const float* __restrict__ z, const float* __restrict__ emb,
             float* __restrict__ oq, float* __restrict__ ost,
             float* __restrict__ oidx)
{
    extern __shared__ char sm[];
    const u32 smb = s2u(sm);
    float* z2s    = (float*)(sm + SZ2);
    int*   rowMin = (int*)(sm + SMIN);
    int*   cnt    = (int*)(sm + SCNT);
    float* candD  = (float*)(sm + SCD);
    int*   candK  = (int*)(sm + SCK);
    int*   fidx   = (int*)(sm + SFI);

    const int tid  = threadIdx.x;
    const int wid  = tid >> 5;
    const int lane = tid & 31;
    const int rowbase = blockIdx.x * BM;
    const int Rw = (wid & 3) * 32;      // warp M offset (4 warps over M)
    const int Cw = (wid >> 2) * 32;     // warp N offset (2 warps over N)

    if (tid < BM) {
        rowMin[tid] = 0x7f7fffff;       // +FLT_MAX bits (distances positive)
        cnt[tid] = 0;
        z2s[tid] = g_z2[rowbase + tid];
    }

    // group 0: A tile + B tile 0 + e2 tile 0
    {
        const __nv_bfloat16* zb = g_zbf + (size_t)rowbase * DD;
        #pragma unroll 4
        for (int q = tid; q < BM * 32; q += NTHR) {
            int r = q >> 5, c = (q & 31) * 8;
            cpa16(smb + SA + (u32)((r * STRD + c) * 2), zb + (size_t)r * DD + c);
        }
        const __nv_bfloat16* eb = g_ebf;
        #pragma unroll 2
        for (int q = tid; q < BN * 32; q += NTHR) {
            int r = q >> 5, c = (q & 31) * 8;
            cpa16(smb + SB0 + (u32)((r * STRD + c) * 2), eb + (size_t)r * DD + c);
        }
        if (tid < 16) cpa16(smb + SE20 + tid * 16, g_e2 + tid * 4);
        asm volatile("cp.async.commit_group;\n" ::);
    }
    __syncthreads();

    // ldmatrix lane bases
    // A: matrix m = lane>>3: row += 8*(m&1), k += 8*(m>>1)
    const int lrA = (lane & 7) + 8 * ((lane >> 3) & 1);
    const int kA  = 8 * (lane >> 4);
    const u32 aBase = smb + SA + (u32)(((Rw + lrA) * STRD + kA) * 2);
    // B: matrix m = lane>>3: n += 8*(m>>1), k += 8*(m&1)
    const int lrB = (lane & 7) + 8 * (lane >> 4);
    const int kB  = 8 * ((lane >> 3) & 1);
    const u32 bOff = (u32)(((Cw + lrB) * STRD + kB) * 2);

    for (int t = 0; t < NTILES; ++t) {
        if (t + 1 < NTILES) {
            const __nv_bfloat16* eb = g_ebf + (size_t)(t + 1) * BN * DD;
            u32 bb  = smb + (((t + 1) & 1) ? SB1 : SB0);
            u32 e2d = smb + (((t + 1) & 1) ? SE21 : SE20);
            #pragma unroll 2
            for (int q = tid; q < BN * 32; q += NTHR) {
                int r = q >> 5, c = (q & 31) * 8;
                cpa16(bb + (u32)((r * STRD + c) * 2), eb + (size_t)r * DD + c);
            }
            if (tid < 16) cpa16(e2d + tid * 16, g_e2 + (t + 1) * BN + tid * 4);
            asm volatile("cp.async.commit_group;\n" ::);
            asm volatile("cp.async.wait_group 1;\n" ::);
        } else {
            asm volatile("cp.async.wait_group 0;\n" ::);
        }
        __syncthreads();

        const u32 bBase0 = smb + ((t & 1) ? SB1 : SB0) + bOff;
        const float* e2t = (const float*)(sm + ((t & 1) ? SE21 : SE20));

        float acc[2][4][4];
        #pragma unroll
        for (int mi = 0; mi < 2; ++mi)
            #pragma unroll
            for (int ni = 0; ni < 4; ++ni)
                #pragma unroll
                for (int c = 0; c < 4; ++c) acc[mi][ni][c] = 0.f;

        #pragma unroll 4
        for (int ks = 0; ks < 16; ++ks) {
            u32 aT[2][4], bT[2][4];
            ldsm4(aT[0], aBase + (u32)(ks * 32));
            ldsm4(aT[1], aBase + (u32)(16 * STRD * 2 + ks * 32));
            ldsm4(bT[0], bBase0 + (u32)(ks * 32));
            ldsm4(bT[1], bBase0 + (u32)(16 * STRD * 2 + ks * 32));
            #pragma unroll
            for (int mi = 0; mi < 2; ++mi) {
                mma16816(acc[mi][0], aT[mi], &bT[0][0]);
                mma16816(acc[mi][1], aT[mi], &bT[0][2]);
                mma16816(acc[mi][2], aT[mi], &bT[1][0]);
                mma16816(acc[mi][3], aT[mi], &bT[1][2]);
            }
        }

        // ---- epilogue: dv in-place, row-min update, windowed inserts ----
        int cb = t * BN;
        float e2loc[4][2];
        #pragma unroll
        for (int ni = 0; ni < 4; ++ni) {
            float2 v = *(const float2*)(e2t + Cw + ni * 8 + (lane & 3) * 2);
            e2loc[ni][0] = v.x; e2loc[ni][1] = v.y;
        }
        #pragma unroll
        for (int mi = 0; mi < 2; ++mi) {
            #pragma unroll
            for (int s = 0; s < 2; ++s) {
                int r = Rw + mi * 16 + (lane >> 2) + 8 * s;
                float z2v = z2s[r];
                float mn = 3.4e38f;
                #pragma unroll
                for (int ni = 0; ni < 4; ++ni) {
                    #pragma unroll
                    for (int q = 0; q < 2; ++q) {
                        float dv = fmaf(-2.f, acc[mi][ni][2 * s + q], z2v + e2loc[ni][q]);
                        acc[mi][ni][2 * s + q] = dv;
                        mn = fminf(mn, dv);
                    }
                }
                if (__float_as_int(mn) < rowMin[r])
                    atomicMin(&rowMin[r], __float_as_int(mn));
            }
        }
        if (t == 0) __syncthreads();   // tile 0: establish thresholds first
        #pragma unroll
        for (int mi = 0; mi < 2; ++mi) {
            #pragma unroll
            for (int s = 0; s < 2; ++s) {
                int r = Rw + mi * 16 + (lane >> 2) + 8 * s;
                float thr = __int_as_float(rowMin[r]) + WIN;
                #pragma unroll
                for (int ni = 0; ni < 4; ++ni) {
                    #pragma unroll
                    for (int q = 0; q < 2; ++q) {
                        float dv = acc[mi][ni][2 * s + q];
                        if (dv <= thr) {
                            int pos = atomicAdd(&cnt[r], 1);
                            if (pos < CAP) {
                                candD[r * CAP + pos] = dv;
                                candK[r * CAP + pos] = cb + Cw + ni * 8 + (lane & 3) * 2 + q;
                            }
                        }
                    }
                }
            }
        }
        __syncthreads();
    }

    // ---- exact rescore (replicates R2 arithmetic exactly) ----
    if (tid < BM) {
        int r = tid;
        size_t n = (size_t)rowbase + r;
        int c = cnt[r];
        if (c > CAP) {
            fidx[r] = -1;
        } else {
            float thrF = __int_as_float(rowMin[r]) + WIN;
            float z2e = g_z2[n];
            const float* zr = z + n * DD;
            float bd = 0.f; int bk = -1;
            for (int i = 0; i < c; ++i) {
                if (candD[r * CAP + i] > thrF) continue;
                int k = candK[r * CAP + i];
                const float* er = emb + (size_t)k * DD;
                float lo = 0.f, hi = 0.f;
                #pragma unroll 4
                for (int d2 = 0; d2 < DD / 2; ++d2) {
                    lo = __fmaf_rn(__ldg(zr + 2 * d2),     __ldg(er + 2 * d2),     lo);
                    hi = __fmaf_rn(__ldg(zr + 2 * d2 + 1), __ldg(er + 2 * d2 + 1), hi);
                }
                float dot = __fadd_rn(lo, hi);
                float tt  = __fadd_rn(z2e, g_e2[k]);
                float dd  = __fadd_rn(tt, -2.0f * dot);
                if (bk < 0 || dd < bd || (dd == bd && k < bk)) { bd = dd; bk = k; }
            }
            fidx[r] = bk;
        }
    }
    __syncthreads();

    // ---- overflow fallback: full exact scan (cold) ----
    {
        float* redD = (float*)(sm + SB0);
        int*   redI = (int*)(sm + SB0 + NTHR * 4);
        for (int r = 0; r < BM; ++r) {
            if (fidx[r] != -1) continue;
            size_t n = (size_t)rowbase + r;
            const float* zr = z + n * DD;
            float z2e = g_z2[n];
            float bd = 0.f; int bk = -1;
            for (int k = tid; k < KC; k += NTHR) {
                const float* er = emb + (size_t)k * DD;
                float lo = 0.f, hi = 0.f;
                #pragma unroll 4
                for (int d2 = 0; d2 < DD / 2; ++d2) {
                    lo = __fmaf_rn(zr[2 * d2],     er[2 * d2],     lo);
                    hi = __fmaf_rn(zr[2 * d2 + 1], er[2 * d2 + 1], hi);
                }
                float dot = __fadd_rn(lo, hi);
                float dd  = __fadd_rn(__fadd_rn(z2e, g_e2[k]), -2.0f * dot);
                if (bk < 0 || dd < bd || (dd == bd && k < bk)) { bd = dd; bk = k; }
            }
            redD[tid] = bd; redI[tid] = bk;
            __syncthreads();
            if (tid == 0) {
                float B = redD[0]; int K2 = redI[0];
                for (int s2 = 1; s2 < NTHR; ++s2) {
                    float d = redD[s2]; int k2 = redI[s2];
                    if (k2 >= 0 && (K2 < 0 || d < B || (d == B && k2 < K2))) { B = d; K2 = k2; }
                }
                fidx[r] = K2;
            }
            __syncthreads();
        }
    }
    __syncthreads();

    // ---- outputs ----
    for (int r = 0; r < BM; ++r) {
        int    idx = fidx[r];
        size_t n   = (size_t)rowbase + r;
        float  qv  = __ldg(emb + (size_t)idx * DD + tid);
        float  zv  = __ldg(z + n * DD + tid);
        if (oq)  oq[n * DD + tid]  = qv;
        if (ost) ost[n * DD + tid] = __fadd_rn(__fadd_rn(qv, -zv), zv);
    }
    if (oidx && tid < BM)
        oidx[(size_t)rowbase + tid] = (float)fidx[tid];
}

extern "C" void kernel_launch(void* const* d_in, const int* in_sizes, int n_in,
                              void* d_out, int out_size)
{
    const float* z   = (const float*)d_in[0];
    const float* emb = (const float*)d_in[1];
    float* out = (float*)d_out;

    const int N = in_sizes[0] / DD;
    const size_t ND = (size_t)N * DD;

    float *oq = nullptr, *ost = nullptr, *oidx = nullptr;
    long osz = (long)out_size;
    if (osz >= (long)(2 * ND + N)) { oq = out; ost = out + ND; oidx = out + 2 * ND; }
    else if (osz == (long)(ND + N)) { oq = out; oidx = out + ND; }
    else if (osz == (long)ND)       { oq = out; }
    else if (osz == (long)N)        { oidx = out; }
    else                            { oq = out; }

    prep_e<<<KC, 32>>>(emb);
    prep_z<<<N, 32>>>(z);

    cudaFuncSetAttribute(vq_main, cudaFuncAttributeMaxDynamicSharedMemorySize, STOT);
    vq_main<<<N / BM, NTHR, STOT>>>(z, emb, oq, ost, oidx);
}